// round 1
// baseline (speedup 1.0000x reference)
#include <cuda_runtime.h>
#include <math.h>

// Problem constants
#define BB    32
#define LL1   64
#define LL2   64
#define HH    256
#define FEATF 512   // per-sequence feature dim
// W is [HH, 4*256] = [256, 1024] row-major. W1 = W[:, :512], W2 = W[:, 512:]

// Scratch: y1[b*64+i][h], y2b[b*64+j][h] (bias folded into y2b)
__device__ float g_y1[BB * LL1 * HH];   // 2 MB
__device__ float g_y2[BB * LL2 * HH];   // 2 MB

__device__ __forceinline__ unsigned long long pack2(float lo, float hi) {
    unsigned long long r;
    asm("mov.b64 %0, {%1, %2};" : "=l"(r) : "f"(lo), "f"(hi));
    return r;
}
__device__ __forceinline__ unsigned long long fma2(unsigned long long a,
                                                   unsigned long long b,
                                                   unsigned long long c) {
    unsigned long long d;
    asm("fma.rn.f32x2 %0, %1, %2, %3;" : "=l"(d) : "l"(a), "l"(b), "l"(c));
    return d;
}
__device__ __forceinline__ void unpack2(unsigned long long v, float& lo, float& hi) {
    asm("mov.b64 {%0, %1}, %2;" : "=f"(lo), "=f"(hi) : "l"(v));
}

// ---------------------------------------------------------------------------
// GEMM: Y[r, h], r in [0,4096). r<2048: x1 @ W[:, :512]^T -> g_y1
//                               r>=2048: x2 @ W[:, 512:]^T + bias -> g_y2
// 64x64 tile, BK=16, 256 threads, 4x4 micro-tile, f32x2 packed accumulators.
// ---------------------------------------------------------------------------
__global__ void __launch_bounds__(256)
gemm_kernel(const float* __restrict__ x1, const float* __restrict__ x2,
            const float* __restrict__ W, const float* __restrict__ bias)
{
    const int colBase = blockIdx.x * 64;          // h
    const int rowBase = blockIdx.y * 64;          // global row in [0,4096)
    const int half    = (rowBase >= 2048) ? 1 : 0;
    const float* __restrict__ X = half ? x2 : x1;
    const int rowLoc = rowBase - half * 2048;
    const int wOff   = half ? FEATF : 0;

    __shared__ float As[16][68];  // [k][m], padded
    __shared__ float Bs[16][68];  // [k][n], padded

    const int tid = threadIdx.x;
    const int tx = tid & 15;      // n group
    const int ty = tid >> 4;      // m group
    const int lr = tid >> 2;      // 0..63: load row within tile
    const int lk = (tid & 3) * 4; // 0,4,8,12: load k offset

    const float* Aptr = X + (rowLoc + lr) * FEATF + lk;
    const float* Bptr = W + (colBase + lr) * (4 * HH) + wOff + lk;

    unsigned long long acc[2][4];
#pragma unroll
    for (int mp = 0; mp < 2; mp++)
#pragma unroll
        for (int n = 0; n < 4; n++) acc[mp][n] = 0ULL;  // (0.f, 0.f)

    // prefetch first tile
    float4 a4 = *(const float4*)(Aptr);
    float4 b4 = *(const float4*)(Bptr);

    for (int k0 = 0; k0 < FEATF; k0 += 16) {
        __syncthreads();
        As[lk + 0][lr] = a4.x; As[lk + 1][lr] = a4.y;
        As[lk + 2][lr] = a4.z; As[lk + 3][lr] = a4.w;
        Bs[lk + 0][lr] = b4.x; Bs[lk + 1][lr] = b4.y;
        Bs[lk + 2][lr] = b4.z; Bs[lk + 3][lr] = b4.w;
        __syncthreads();

        if (k0 + 16 < FEATF) {   // prefetch next tile into registers
            a4 = *(const float4*)(Aptr + k0 + 16);
            b4 = *(const float4*)(Bptr + k0 + 16);
        }

#pragma unroll
        for (int k = 0; k < 16; k++) {
            float4 av = *(const float4*)&As[k][ty * 4];
            float4 bv = *(const float4*)&Bs[k][tx * 4];
            unsigned long long am0 = pack2(av.x, av.y);
            unsigned long long am1 = pack2(av.z, av.w);
#pragma unroll
            for (int n = 0; n < 4; n++) {
                float bn = (n == 0) ? bv.x : (n == 1) ? bv.y : (n == 2) ? bv.z : bv.w;
                unsigned long long bd = pack2(bn, bn);
                acc[0][n] = fma2(am0, bd, acc[0][n]);
                acc[1][n] = fma2(am1, bd, acc[1][n]);
            }
        }
    }

    float* __restrict__ Y = half ? g_y2 : g_y1;
#pragma unroll
    for (int mp = 0; mp < 2; mp++) {
#pragma unroll
        for (int n = 0; n < 4; n++) {
            float lo, hi;
            unpack2(acc[mp][n], lo, hi);
            const int col = colBase + tx * 4 + n;
            const float bb = half ? bias[col] : 0.0f;
            const int r0 = rowLoc + ty * 4 + mp * 2;
            Y[r0 * HH + col]       = lo + bb;
            Y[(r0 + 1) * HH + col] = hi + bb;
        }
    }
}

// ---------------------------------------------------------------------------
// Pair reduction:
// out[b,h] = ( sum_{i<sl1, j<sl2} relu(y1[b,i,h] + y2b[b,j,h])
//              + (4096 - sl1*sl2) * relu(bias[h]) ) / (sl1*sl2)
// Grid: (H/32, B). 256 threads: h = tid&31, jg = tid>>5 (8 j's each).
// Masked j handled branch-free via t2 = -inf  =>  max(v + -inf, 0) = 0.
// ---------------------------------------------------------------------------
__global__ void __launch_bounds__(256)
pairsum_kernel(const int* __restrict__ sl1p, const int* __restrict__ sl2p,
               const float* __restrict__ bias, float* __restrict__ out)
{
    const int b     = blockIdx.y;
    const int hbase = blockIdx.x * 32;
    const int tid   = threadIdx.x;
    const int h     = tid & 31;
    const int jg    = tid >> 5;    // 0..7

    const int sl1 = sl1p[b];
    const int sl2 = sl2p[b];

    __shared__ float y1s[LL1 * 32];
    for (int t = tid; t < LL1 * 32; t += 256) {
        int i = t >> 5, hh = t & 31;
        y1s[t] = g_y1[(b * LL1 + i) * HH + hbase + hh];
    }
    __syncthreads();

    float t2[8];
#pragma unroll
    for (int k = 0; k < 8; k++) {
        int j = jg * 8 + k;
        t2[k] = (j < sl2) ? g_y2[(b * LL2 + j) * HH + hbase + h] : -INFINITY;
    }

    float acc[8];
#pragma unroll
    for (int k = 0; k < 8; k++) acc[k] = 0.0f;

    for (int i = 0; i < sl1; i++) {
        float v = y1s[i * 32 + h];
#pragma unroll
        for (int k = 0; k < 8; k++)
            acc[k] += fmaxf(v + t2[k], 0.0f);
    }

    float part = 0.0f;
#pragma unroll
    for (int k = 0; k < 8; k++) part += acc[k];

    __shared__ float red[8][32];
    red[jg][h] = part;
    __syncthreads();

    if (jg == 0) {
        float s = 0.0f;
#pragma unroll
        for (int g = 0; g < 8; g++) s += red[g][h];
        const float rb = fmaxf(bias[hbase + h], 0.0f);
        const float np = (float)(sl1 * sl2);
        s += ((float)(LL1 * LL2) - np) * rb;
        out[b * HH + hbase + h] = s / np;
    }
}

extern "C" void kernel_launch(void* const* d_in, const int* in_sizes, int n_in,
                              void* d_out, int out_size)
{
    const float* x1   = (const float*)d_in[0];
    const int*   sl1  = (const int*)  d_in[1];
    const float* x2   = (const float*)d_in[2];
    const int*   sl2  = (const int*)  d_in[3];
    const float* W    = (const float*)d_in[4];
    const float* bias = (const float*)d_in[5];
    float* out = (float*)d_out;

    dim3 gGemm(HH / 64, 4096 / 64);      // 4 x 64 = 256 blocks
    gemm_kernel<<<gGemm, 256>>>(x1, x2, W, bias);

    dim3 gPair(HH / 32, BB);             // 8 x 32 = 256 blocks
    pairsum_kernel<<<gPair, 256>>>(sl1, sl2, bias, out);
}

// round 4
// speedup vs baseline: 1.9082x; 1.9082x over previous
#include <cuda_runtime.h>
#include <math.h>
#include <stdint.h>

#define BB    32
#define LL1   64
#define LL2   64
#define HH    256
#define FEATF 512

// Scratch
__device__ float g_y1[BB * LL1 * HH];     // x1 @ W1^T
__device__ float g_y2[BB * LL2 * HH];     // x2 @ W2^T + bias
__device__ float g_part[4 * BB * HH];     // pairsum partials [s][b][h]

// ---------------------------------------------------------------------------
// GEMM via mma.sync tf32 (sm_80+ baseline feature; valid on sm_103 target)
// Y[4096, 256] = [x1;x2] @ [W1;W2]^T, bias folded into the x2 half.
// CTA tile 64(m) x 128(n), K chunks of 32, cp.async double buffer.
// 8 warps = 2(m) x 4(n); warp tile 32x32; mma m16n8k8.
// ---------------------------------------------------------------------------
#define TM   64
#define TN   128
#define TKC  32
#define PADS 36                       // floats per smem row (32 data + 4 pad)
#define A_STAGE_B (TM * PADS * 4)     // 9216 B
#define B_STAGE_B (TN * PADS * 4)     // 18432 B
#define SMEM_GEMM (2 * A_STAGE_B + 2 * B_STAGE_B)   // 55296 B

__device__ __forceinline__ uint32_t f2tf32(float f) {
    uint32_t r;
    asm("cvt.rna.tf32.f32 %0, %1;" : "=r"(r) : "f"(f));
    return r;
}
__device__ __forceinline__ void mma_tf32(float* c, const uint32_t* a, const uint32_t* b) {
    asm volatile(
        "mma.sync.aligned.m16n8k8.row.col.f32.tf32.tf32.f32 "
        "{%0,%1,%2,%3}, {%4,%5,%6,%7}, {%8,%9}, {%0,%1,%2,%3};"
        : "+f"(c[0]), "+f"(c[1]), "+f"(c[2]), "+f"(c[3])
        : "r"(a[0]), "r"(a[1]), "r"(a[2]), "r"(a[3]), "r"(b[0]), "r"(b[1]));
}
__device__ __forceinline__ void cp16(uint32_t dst, const void* src) {
    asm volatile("cp.async.cg.shared.global [%0], [%1], 16;" :: "r"(dst), "l"(src));
}
__device__ __forceinline__ uint32_t smem_u32(const void* p) {
    uint32_t a;
    asm("{ .reg .u64 t; cvta.to.shared.u64 t, %1; cvt.u32.u64 %0, t; }"
        : "=r"(a) : "l"(p));
    return a;
}

__global__ void __launch_bounds__(256)
gemm_mma(const float* __restrict__ x1, const float* __restrict__ x2,
         const float* __restrict__ W, const float* __restrict__ bias)
{
    extern __shared__ __align__(16) char smem[];
    const uint32_t sb = smem_u32(smem);
    const int tid = threadIdx.x;
    const int wid = tid >> 5, lane = tid & 31;
    const int g = lane >> 2, t = lane & 3;

    const int mT = blockIdx.x;              // 0..63
    const int nT = blockIdx.y;              // 0..1
    const int half = (mT >= 32) ? 1 : 0;
    const float* __restrict__ X = half ? x2 : x1;
    const int rowLoc = (mT & 31) * TM;      // row within its 2048-row half
    const int hBase  = nT * TN;
    const int wOff   = half ? FEATF : 0;

    const int wm = wid & 1;                 // m warp: 0..1
    const int wn = wid >> 1;                // n warp: 0..3
    const int mW = wm * 32;                 // warp m offset in tile
    const int nW = wn * 32;                 // warp n offset in tile

    // Stage loaders (row-major, 32 floats data per row, PADS stride)
    auto loadA = [&](int s, int k0) {
        const uint32_t base = sb + s * A_STAGE_B;
        #pragma unroll
        for (int q = 0; q < 2; q++) {
            int idx = tid + q * 256;        // 0..511
            int row = idx >> 3, seg = idx & 7;
            cp16(base + (row * PADS + seg * 4) * 4,
                 X + (size_t)(rowLoc + row) * FEATF + k0 + seg * 4);
        }
    };
    auto loadB = [&](int s, int k0) {
        const uint32_t base = sb + 2 * A_STAGE_B + s * B_STAGE_B;
        #pragma unroll
        for (int q = 0; q < 4; q++) {
            int idx = tid + q * 256;        // 0..1023
            int row = idx >> 3, seg = idx & 7;
            cp16(base + (row * PADS + seg * 4) * 4,
                 W + (size_t)(hBase + row) * (4 * HH) + wOff + k0 + seg * 4);
        }
    };

    float acc[2][4][4];
    #pragma unroll
    for (int mf = 0; mf < 2; mf++)
        #pragma unroll
        for (int nf = 0; nf < 4; nf++)
            #pragma unroll
            for (int r = 0; r < 4; r++) acc[mf][nf][r] = 0.0f;

    loadA(0, 0); loadB(0, 0);
    asm volatile("cp.async.commit_group;" ::: "memory");

    const int NCH = FEATF / TKC;            // 16
    for (int c = 0; c < NCH; c++) {
        if (c + 1 < NCH) {
            loadA((c + 1) & 1, (c + 1) * TKC);
            loadB((c + 1) & 1, (c + 1) * TKC);
            asm volatile("cp.async.commit_group;" ::: "memory");
            asm volatile("cp.async.wait_group 1;" ::: "memory");
        } else {
            asm volatile("cp.async.wait_group 0;" ::: "memory");
        }
        __syncthreads();

        const int s = c & 1;
        const float* As = (const float*)(smem + s * A_STAGE_B);
        const float* Bs = (const float*)(smem + 2 * A_STAGE_B + s * B_STAGE_B);

        #pragma unroll
        for (int kk = 0; kk < TKC; kk += 8) {
            uint32_t a[2][4], b[4][2];
            #pragma unroll
            for (int mf = 0; mf < 2; mf++) {
                const int br = mW + mf * 16;
                a[mf][0] = f2tf32(As[(br + g)     * PADS + kk + t]);
                a[mf][1] = f2tf32(As[(br + 8 + g) * PADS + kk + t]);
                a[mf][2] = f2tf32(As[(br + g)     * PADS + kk + t + 4]);
                a[mf][3] = f2tf32(As[(br + 8 + g) * PADS + kk + t + 4]);
            }
            #pragma unroll
            for (int nf = 0; nf < 4; nf++) {
                const int bn = nW + nf * 8 + g;
                b[nf][0] = f2tf32(Bs[bn * PADS + kk + t]);
                b[nf][1] = f2tf32(Bs[bn * PADS + kk + t + 4]);
            }
            #pragma unroll
            for (int mf = 0; mf < 2; mf++)
                #pragma unroll
                for (int nf = 0; nf < 4; nf++)
                    mma_tf32(acc[mf][nf], a[mf], b[nf]);
        }
        __syncthreads();
    }

    // Epilogue: direct stores (float2), bias folded on the x2 half.
    float* __restrict__ Y = half ? g_y2 : g_y1;
    #pragma unroll
    for (int mf = 0; mf < 2; mf++) {
        #pragma unroll
        for (int nf = 0; nf < 4; nf++) {
            const int row = rowLoc + mW + mf * 16 + g;
            const int h   = hBase + nW + nf * 8 + 2 * t;
            float v0 = acc[mf][nf][0], v1 = acc[mf][nf][1];
            float v2 = acc[mf][nf][2], v3 = acc[mf][nf][3];
            if (half) {
                const float b0 = __ldg(&bias[h]), b1 = __ldg(&bias[h + 1]);
                v0 += b0; v1 += b1; v2 += b0; v3 += b1;
            }
            *(float2*)&Y[(size_t)row * HH + h]       = make_float2(v0, v1);
            *(float2*)&Y[(size_t)(row + 8) * HH + h] = make_float2(v2, v3);
        }
    }
}

// ---------------------------------------------------------------------------
// Pair reduction (partial over i-chunk of 16):
// g_part[s][b][hb*32+h] = sum_{i in chunk, i<sl1} sum_{j<sl2} relu(y1+y2b)
// Grid (8, 32, 4), 256 threads: h = tid&31, jg = tid>>5 (8 j's each).
// ---------------------------------------------------------------------------
__global__ void __launch_bounds__(256)
pairsum_kernel(const int* __restrict__ sl1p, const int* __restrict__ sl2p)
{
    const int b  = blockIdx.y;
    const int hb = blockIdx.x;          // h chunk of 32
    const int s  = blockIdx.z;          // i chunk of 16
    const int tid = threadIdx.x;
    const int h  = tid & 31;
    const int jg = tid >> 5;

    const int sl1 = sl1p[b];
    const int sl2 = sl2p[b];
    const int i0  = s * 16;

    float* part = &g_part[((s * BB + b) * 8 + hb) * 32];
    if (i0 >= sl1) {
        if (tid < 32) part[tid] = 0.0f;
        return;
    }

    __shared__ float y1s[16 * 32];
    {
        int i = tid >> 5, hh = tid & 31;
        y1s[tid]       = g_y1[(b * LL1 + i0 + i)     * HH + hb * 32 + hh];
        y1s[tid + 256] = g_y1[(b * LL1 + i0 + 8 + i) * HH + hb * 32 + hh];
    }
    __syncthreads();

    float t2[8];
    #pragma unroll
    for (int k = 0; k < 8; k++) {
        int j = jg * 8 + k;
        t2[k] = (j < sl2) ? g_y2[(b * LL2 + j) * HH + hb * 32 + h] : -INFINITY;
    }

    const int niter = min(16, sl1 - i0);
    float acc[8];
    #pragma unroll
    for (int k = 0; k < 8; k++) acc[k] = 0.0f;

    for (int i = 0; i < niter; i++) {
        float v = y1s[i * 32 + h];
        #pragma unroll
        for (int k = 0; k < 8; k++)
            acc[k] += fmaxf(v + t2[k], 0.0f);
    }

    float p = 0.0f;
    #pragma unroll
    for (int k = 0; k < 8; k++) p += acc[k];

    __shared__ float red[8][32];
    red[jg][h] = p;
    __syncthreads();
    if (jg == 0) {
        float ss = 0.0f;
        #pragma unroll
        for (int gg = 0; gg < 8; gg++) ss += red[gg][h];
        part[h] = ss;
    }
}

// ---------------------------------------------------------------------------
// Final reduce: sum 4 partials, add zero-pad bias term, divide.
// ---------------------------------------------------------------------------
__global__ void __launch_bounds__(256)
reduce_kernel(const int* __restrict__ sl1p, const int* __restrict__ sl2p,
              const float* __restrict__ bias, float* __restrict__ out)
{
    const int b = blockIdx.x;
    const int h = threadIdx.x;
    const int hb = h >> 5, hh = h & 31;
    float ssum = 0.0f;
    #pragma unroll
    for (int st = 0; st < 4; st++)
        ssum += g_part[((st * BB + b) * 8 + hb) * 32 + hh];
    const float n = (float)(sl1p[b] * sl2p[b]);
    const float rb = fmaxf(bias[h], 0.0f);
    out[b * HH + h] = (ssum + ((float)(LL1 * LL2) - n) * rb) / n;
}

extern "C" void kernel_launch(void* const* d_in, const int* in_sizes, int n_in,
                              void* d_out, int out_size)
{
    const float* x1   = (const float*)d_in[0];
    const int*   sl1  = (const int*)  d_in[1];
    const float* x2   = (const float*)d_in[2];
    const int*   sl2  = (const int*)  d_in[3];
    const float* W    = (const float*)d_in[4];
    const float* bias = (const float*)d_in[5];
    float* out = (float*)d_out;

    static int smemSet = 0;
    if (!smemSet) {
        cudaFuncSetAttribute(gemm_mma, cudaFuncAttributeMaxDynamicSharedMemorySize,
                             SMEM_GEMM);
        smemSet = 1;
    }

    gemm_mma<<<dim3(64, 2), 256, SMEM_GEMM>>>(x1, x2, W, bias);
    pairsum_kernel<<<dim3(8, 32, 4), 256>>>(sl1, sl2);
    reduce_kernel<<<32, 256>>>(sl1, sl2, bias, out);
}